// round 1
// baseline (speedup 1.0000x reference)
#include <cuda_runtime.h>

#define Wd 128
#define Hd 128
#define Dd 128
#define HWd (Hd*Wd)
#define VOX (Dd*Hd*Wd)
#define NS 16
#define NPIX (NS*128*128)

// ---------------- device state (CG vectors + scalars) ----------------
__device__ float g_b[VOX];
__device__ float g_x[VOX];
__device__ float g_r[VOX];
__device__ float g_p[VOX];
__device__ float g_Ap[VOX];
__device__ double g_rr;
__device__ double g_dots[2];   // [0] = p.Ap accumulator, [1] = rr_new accumulator
__device__ float g_alpha, g_beta;

// ---------------- helpers ----------------
__device__ __forceinline__ float tri_gather(const float* __restrict__ v,
                                            float px, float py, float pz) {
    float fx0 = floorf(px), fy0 = floorf(py), fz0 = floorf(pz);
    int x0 = (int)fx0, y0 = (int)fy0, z0 = (int)fz0;
    float fx = px - fx0, fy = py - fy0, fz = pz - fz0;
    float gx = 1.f - fx, gy = 1.f - fy, gz = 1.f - fz;
    if (((unsigned)x0 < (unsigned)(Wd-1)) & ((unsigned)y0 < (unsigned)(Hd-1)) &
        ((unsigned)z0 < (unsigned)(Dd-1))) {
        int i = (z0*Hd + y0)*Wd + x0;
        float v000 = v[i],        v001 = v[i+1];
        float v010 = v[i+Wd],     v011 = v[i+Wd+1];
        float v100 = v[i+HWd],    v101 = v[i+HWd+1];
        float v110 = v[i+HWd+Wd], v111 = v[i+HWd+Wd+1];
        float a0 = gy*(gx*v000 + fx*v001) + fy*(gx*v010 + fx*v011);
        float a1 = gy*(gx*v100 + fx*v101) + fy*(gx*v110 + fx*v111);
        return gz*a0 + fz*a1;
    }
    float wxa[2] = {gx, fx}, wya[2] = {gy, fy}, wza[2] = {gz, fz};
    float s = 0.f;
    #pragma unroll
    for (int dz = 0; dz < 2; ++dz) {
        int zi = z0 + dz; if ((unsigned)zi >= (unsigned)Dd) continue;
        #pragma unroll
        for (int dy = 0; dy < 2; ++dy) {
            int yi = y0 + dy; if ((unsigned)yi >= (unsigned)Hd) continue;
            #pragma unroll
            for (int dx = 0; dx < 2; ++dx) {
                int xi = x0 + dx; if ((unsigned)xi >= (unsigned)Wd) continue;
                s += wza[dz]*wya[dy]*wxa[dx] * v[(zi*Hd + yi)*Wd + xi];
            }
        }
    }
    return s;
}

__device__ __forceinline__ void tri_scatter(float* __restrict__ d,
                                            float px, float py, float pz, float val) {
    float fx0 = floorf(px), fy0 = floorf(py), fz0 = floorf(pz);
    int x0 = (int)fx0, y0 = (int)fy0, z0 = (int)fz0;
    float fx = px - fx0, fy = py - fy0, fz = pz - fz0;
    float gx = 1.f - fx, gy = 1.f - fy, gz = 1.f - fz;
    if (((unsigned)x0 < (unsigned)(Wd-1)) & ((unsigned)y0 < (unsigned)(Hd-1)) &
        ((unsigned)z0 < (unsigned)(Dd-1))) {
        int i = (z0*Hd + y0)*Wd + x0;
        float vx0 = val*gx, vx1 = val*fx;
        float w00 = gy*gz, w10 = fy*gz, w01 = gy*fz, w11 = fy*fz;
        atomicAdd(&d[i],           vx0*w00);
        atomicAdd(&d[i+1],         vx1*w00);
        atomicAdd(&d[i+Wd],        vx0*w10);
        atomicAdd(&d[i+Wd+1],      vx1*w10);
        atomicAdd(&d[i+HWd],       vx0*w01);
        atomicAdd(&d[i+HWd+1],     vx1*w01);
        atomicAdd(&d[i+HWd+Wd],    vx0*w11);
        atomicAdd(&d[i+HWd+Wd+1],  vx1*w11);
        return;
    }
    float wxa[2] = {gx, fx}, wya[2] = {gy, fy}, wza[2] = {gz, fz};
    #pragma unroll
    for (int dz = 0; dz < 2; ++dz) {
        int zi = z0 + dz; if ((unsigned)zi >= (unsigned)Dd) continue;
        #pragma unroll
        for (int dy = 0; dy < 2; ++dy) {
            int yi = y0 + dy; if ((unsigned)yi >= (unsigned)Hd) continue;
            #pragma unroll
            for (int dx = 0; dx < 2; ++dx) {
                int xi = x0 + dx; if ((unsigned)xi >= (unsigned)Wd) continue;
                atomicAdd(&d[(zi*Hd + yi)*Wd + xi], val*wza[dz]*wya[dy]*wxa[dx]);
            }
        }
    }
}

__device__ __forceinline__ double block_reduce_sum(double v) {
    #pragma unroll
    for (int o = 16; o; o >>= 1) v += __shfl_down_sync(0xffffffffu, v, o);
    __shared__ double sh[8];
    int lane = threadIdx.x & 31, wid = threadIdx.x >> 5;
    if (lane == 0) sh[wid] = v;
    __syncthreads();
    if (wid == 0) {
        v = (lane < (int)(blockDim.x >> 5)) ? sh[lane] : 0.0;
        #pragma unroll
        for (int o = 4; o; o >>= 1) v += __shfl_down_sync(0xffffffffu, v, o);
    }
    return v;
}

// ---------------- fused A / AtA projector ----------------
// GATHER=true : dst += At( diag PSF-trilinear gather of src )  (AtA step; src is a volume)
// GATHER=false: dst += At(src) where src is slices[N,1,HS,WS]  (b = At(slices))
template<bool GATHER>
__global__ void __launch_bounds__(256) proj_kernel(
    const float* __restrict__ src, float* __restrict__ dst,
    const float* __restrict__ theta, const float* __restrict__ psf)
{
    int pid = blockIdx.x * 256 + threadIdx.x;
    if (pid >= NPIX) return;
    int n = pid >> 14;
    int h = (pid >> 7) & 127;
    int w = pid & 127;

    const float* T = theta + n*12;
    float c0x = T[0], c1x = T[1], c2x = T[2];
    float c0y = T[4], c1y = T[5], c2y = T[6];
    float c0z = T[8], c1z = T[9], c2z = T[10];

    float u = ((float)w - 63.5f) * 1.5f;
    float v = ((float)h - 63.5f) * 1.5f;
    float bx = u*c0x + v*c1x + T[3]  + 63.5f;
    float by = u*c0y + v*c1y + T[7]  + 63.5f;
    float bz = u*c0z + v*c1z + T[11] + 63.5f;

    // whole 27-sample footprint (margin sqrt(3)) outside volume -> nothing to do
    if (bx < -2.8f || bx > 129.8f || by < -2.8f || by > 129.8f ||
        bz < -2.8f || bz > 129.8f) return;

    float s;
    if (GATHER) {
        s = 0.f;
        for (int kz = 0; kz < 3; ++kz) {
            float oz = (float)(kz - 1);
            float zx = fmaf(oz, c2x, bx), zy = fmaf(oz, c2y, by), zz = fmaf(oz, c2z, bz);
            for (int ky = 0; ky < 3; ++ky) {
                float oy = (float)(ky - 1);
                float yx = fmaf(oy, c1x, zx), yy = fmaf(oy, c1y, zy), yz = fmaf(oy, c1z, zz);
                #pragma unroll
                for (int kx = 0; kx < 3; ++kx) {
                    float ox = (float)(kx - 1);
                    float px = fmaf(ox, c0x, yx), py = fmaf(ox, c0y, yy), pz = fmaf(ox, c0z, yz);
                    s += psf[(kz*3 + ky)*3 + kx] * tri_gather(src, px, py, pz);
                }
            }
        }
    } else {
        s = src[pid];
    }

    for (int kz = 0; kz < 3; ++kz) {
        float oz = (float)(kz - 1);
        float zx = fmaf(oz, c2x, bx), zy = fmaf(oz, c2y, by), zz = fmaf(oz, c2z, bz);
        for (int ky = 0; ky < 3; ++ky) {
            float oy = (float)(ky - 1);
            float yx = fmaf(oy, c1x, zx), yy = fmaf(oy, c1y, zy), yz = fmaf(oy, c1z, zz);
            #pragma unroll
            for (int kx = 0; kx < 3; ++kx) {
                float ox = (float)(kx - 1);
                float px = fmaf(ox, c0x, yx), py = fmaf(ox, c0y, yy), pz = fmaf(ox, c0z, yz);
                tri_scatter(dst, px, py, pz, s * psf[(kz*3 + ky)*3 + kx]);
            }
        }
    }
}

// ---------------- CG vector kernels ----------------
__global__ void zero_init_kernel() {
    for (int i = blockIdx.x*blockDim.x + threadIdx.x; i < VOX; i += gridDim.x*blockDim.x) {
        g_b[i] = 0.f; g_Ap[i] = 0.f;
    }
    if (blockIdx.x == 0 && threadIdx.x == 0) { g_rr = 0.0; g_dots[0] = 0.0; g_dots[1] = 0.0; }
}

__global__ void init_kernel(const float* __restrict__ vol) {
    double acc = 0.0;
    for (int i = blockIdx.x*blockDim.x + threadIdx.x; i < VOX; i += gridDim.x*blockDim.x) {
        g_x[i] = vol[i];
        float r = g_b[i] - g_Ap[i];
        g_r[i] = r; g_p[i] = r; g_Ap[i] = 0.f;
        acc += (double)r * (double)r;
    }
    acc = block_reduce_sum(acc);
    if (threadIdx.x == 0) atomicAdd(&g_rr, acc);
}

__global__ void dot_pAp_kernel() {
    double acc = 0.0;
    for (int i = blockIdx.x*blockDim.x + threadIdx.x; i < VOX; i += gridDim.x*blockDim.x)
        acc += (double)g_p[i] * (double)g_Ap[i];
    acc = block_reduce_sum(acc);
    if (threadIdx.x == 0) atomicAdd(&g_dots[0], acc);
}

__global__ void alpha_kernel() {
    g_alpha = (float)(g_rr / g_dots[0]);
    g_dots[1] = 0.0;
}

__global__ void update_xr_kernel() {
    float a = g_alpha;
    double acc = 0.0;
    for (int i = blockIdx.x*blockDim.x + threadIdx.x; i < VOX; i += gridDim.x*blockDim.x) {
        g_x[i] = fmaf(a, g_p[i], g_x[i]);
        float r = fmaf(-a, g_Ap[i], g_r[i]);
        g_r[i] = r;
        acc += (double)r * (double)r;
    }
    acc = block_reduce_sum(acc);
    if (threadIdx.x == 0) atomicAdd(&g_dots[1], acc);
}

__global__ void beta_kernel() {
    g_beta = (float)(g_dots[1] / g_rr);
    g_rr = g_dots[1];
    g_dots[0] = 0.0;
}

__global__ void update_p_kernel() {
    float b = g_beta;
    for (int i = blockIdx.x*blockDim.x + threadIdx.x; i < VOX; i += gridDim.x*blockDim.x) {
        g_p[i] = fmaf(b, g_p[i], g_r[i]);
        g_Ap[i] = 0.f;
    }
}

__global__ void relu_kernel(float* __restrict__ out) {
    int i = blockIdx.x*blockDim.x + threadIdx.x;
    if (i < VOX) out[i] = fmaxf(g_x[i], 0.f);
}

// ---------------- launch ----------------
extern "C" void kernel_launch(void* const* d_in, const int* in_sizes, int n_in,
                              void* d_out, int out_size) {
    const float* theta  = (const float*)d_in[0];   // [16,3,4]
    const float* slices = (const float*)d_in[1];   // [16,1,128,128]
    const float* volume = (const float*)d_in[2];   // [1,1,128,128,128]
    const float* psf    = (const float*)d_in[3];   // [3,3,3]
    float* out = (float*)d_out;

    void *pb_v = nullptr, *pAp_v = nullptr, *pp_v = nullptr;
    cudaGetSymbolAddress(&pb_v,  g_b);
    cudaGetSymbolAddress(&pAp_v, g_Ap);
    cudaGetSymbolAddress(&pp_v,  g_p);
    float* pb  = (float*)pb_v;
    float* pAp = (float*)pAp_v;
    float* pp  = (float*)pp_v;

    const int TB = 256;
    const int VB = 1024;                 // grid-stride blocks for vector kernels
    const int AB = (NPIX + TB - 1) / TB; // projector blocks

    zero_init_kernel<<<VB, TB>>>();
    proj_kernel<false><<<AB, TB>>>(slices, pb,  theta, psf);   // b  = At(slices)
    proj_kernel<true ><<<AB, TB>>>(volume, pAp, theta, psf);   // Ap = AtA(x0)
    init_kernel<<<VB, TB>>>(volume);                           // x=x0, r=p=b-Ap, rr=r.r, Ap=0

    for (int it = 0; it < 10; ++it) {
        proj_kernel<true><<<AB, TB>>>(pp, pAp, theta, psf);    // Ap = AtA(p)
        dot_pAp_kernel<<<VB, TB>>>();                          // dots[0] = p.Ap
        alpha_kernel<<<1, 1>>>();                              // alpha = rr/pAp; dots[1]=0
        update_xr_kernel<<<VB, TB>>>();                        // x+=a p; r-=a Ap; dots[1]=r.r
        beta_kernel<<<1, 1>>>();                               // beta = rr_new/rr; rr=rr_new; dots[0]=0
        update_p_kernel<<<VB, TB>>>();                         // p = r + beta p; Ap = 0
    }

    relu_kernel<<<VOX / TB, TB>>>(out);
}